// round 4
// baseline (speedup 1.0000x reference)
#include <cuda_runtime.h>
#include <cuda_bf16.h>
#include <mma.h>
#include <cstddef>

using namespace nvcuda;

// Problem constants
#define Bc 4
#define Sc 1024
#define Dc 1024
#define Hc 16
#define DKc 64
#define DVc 64
#define Mc (Bc * Sc)        // 4096
#define HDc (Hc * DKc)      // 1024

// Static device scratch
__device__ float g_Qp[Bc * Hc * Sc * DKc];   // [B,H,S,DK]
__device__ float g_Kp[Bc * Hc * Sc * DKc];
__device__ float g_Vp[Bc * Hc * Sc * DVc];
__device__ float g_ctx[Mc * HDc];            // [B,S,H*DV]
__device__ float g_obuf[Mc * Dc];
__device__ float g_attn_fb[(size_t)Bc * Hc * Sc * Sc];
__device__ int   g_mask_mode;

// bf16 fragments (16x16x16)
using bfrag_a  = wmma::fragment<wmma::matrix_a, 16, 16, 16, __nv_bfloat16, wmma::row_major>;
using bfrag_b  = wmma::fragment<wmma::matrix_b, 16, 16, 16, __nv_bfloat16, wmma::row_major>;
using bfrag_bc = wmma::fragment<wmma::matrix_b, 16, 16, 16, __nv_bfloat16, wmma::col_major>;
using bfrag_c  = wmma::fragment<wmma::accumulator, 16, 16, 16, float>;

__device__ __forceinline__ void cvt_store4(__nv_bfloat16* dh, __nv_bfloat16* dl, float4 v) {
    float a[4] = {v.x, v.y, v.z, v.w};
#pragma unroll
    for (int j = 0; j < 4; j++) {
        __nv_bfloat16 h = __float2bfloat16(a[j]);
        dh[j] = h;
        dl[j] = __float2bfloat16(a[j] - __bfloat162float(h));
    }
}

// ---------------------------------------------------------------------------
// Mask dtype detection
// ---------------------------------------------------------------------------
__global__ void detect_mask_kernel(const unsigned int* __restrict__ m) {
    bool allint = true, allfloat = true;
    for (int i = 0; i < 1024; i++) {
        unsigned int w = m[i];
        if (w > 1u) allint = false;
        if (w != 0u && w != 0x3F800000u) allfloat = false;
    }
    g_mask_mode = allint ? 0 : (allfloat ? 2 : 1);
}

// ---------------------------------------------------------------------------
// Unified pipelined split-bf16 GEMM (all GEMMs have K=1024 here).
// BM=128, BN=64, BK=16, double-buffered smem, register-staged prefetch,
// 3-term hi/lo split for ~fp32 accuracy.
// MODE 0: C row-major [*,1024] (+bias)                 (out-proj)
// MODE 1: C to [B,H,S,64], head = blockIdx.x (+bias)   (Q/K/V projections)
// MODE 2: batched per z=blockIdx.y: A=attn[z], B=V[z], C to concat layout
// ---------------------------------------------------------------------------
template <int MODE>
__global__ __launch_bounds__(256)
void gemm_bf16_split(const float* __restrict__ A, const float* __restrict__ W,
                     const float* __restrict__ bias, float* __restrict__ C,
                     int N /*B row stride / cols*/) {
    constexpr int LDA = 24;    // bf16 elems
    constexpr int LDW = 72;
    constexpr int LDST = 68;   // fp32 staging

    __shared__ __align__(16) char buf[34816];
    __nv_bfloat16* Ahi = (__nv_bfloat16*)buf;        // [2][128][24]
    __nv_bfloat16* Alo = Ahi + 2 * 128 * LDA;
    __nv_bfloat16* Whi = Alo + 2 * 128 * LDA;        // [2][16][72]
    __nv_bfloat16* Wlo = Whi + 2 * 16 * LDW;
    float* stg = (float*)buf;                        // [128][68] epilogue reuse

    const int tid = threadIdx.x;
    const int w = tid >> 5;
    const int wm = w >> 1;
    const int wn = w & 1;

    int row0, col0, z = 0;
    const float *Ab, *Bb;
    if (MODE == 2) {
        z = blockIdx.y;
        row0 = blockIdx.x * 128;
        col0 = 0;
        Ab = A + (size_t)z * Sc * Sc;
        Bb = W + (size_t)z * Sc * DVc;
    } else {
        row0 = blockIdx.y * 128;
        col0 = blockIdx.x * 64;
        Ab = A;
        Bb = W;
    }

    const int ar = tid >> 2, ac = (tid & 3) * 4;
    const int wr = tid >> 4, wc = (tid & 15) * 4;

    bfrag_c acc[2][2];
#pragma unroll
    for (int ti = 0; ti < 2; ti++)
#pragma unroll
        for (int tj = 0; tj < 2; tj++) wmma::fill_fragment(acc[ti][tj], 0.0f);

    float4 ra0, ra1, rw;
    ra0 = *(const float4*)&Ab[(size_t)(row0 + ar) * 1024 + ac];
    ra1 = *(const float4*)&Ab[(size_t)(row0 + ar + 64) * 1024 + ac];
    rw  = *(const float4*)&Bb[(size_t)wr * N + col0 + wc];
    cvt_store4(Ahi + ar * LDA + ac, Alo + ar * LDA + ac, ra0);
    cvt_store4(Ahi + (ar + 64) * LDA + ac, Alo + (ar + 64) * LDA + ac, ra1);
    cvt_store4(Whi + wr * LDW + wc, Wlo + wr * LDW + wc, rw);
    __syncthreads();

    for (int kt = 0; kt < 64; kt++) {
        if (kt < 63) {
            int k = (kt + 1) * 16;
            ra0 = *(const float4*)&Ab[(size_t)(row0 + ar) * 1024 + k + ac];
            ra1 = *(const float4*)&Ab[(size_t)(row0 + ar + 64) * 1024 + k + ac];
            rw  = *(const float4*)&Bb[(size_t)(k + wr) * N + col0 + wc];
        }
        const int cur = kt & 1;
        const int cb = cur * 128 * LDA;
        const int wb = cur * 16 * LDW;

        bfrag_a fah[2], fal[2];
        bfrag_b fbh[2], fbl[2];
#pragma unroll
        for (int ti = 0; ti < 2; ti++) {
            wmma::load_matrix_sync(fah[ti], Ahi + cb + (wm * 32 + ti * 16) * LDA, LDA);
            wmma::load_matrix_sync(fal[ti], Alo + cb + (wm * 32 + ti * 16) * LDA, LDA);
        }
#pragma unroll
        for (int tj = 0; tj < 2; tj++) {
            wmma::load_matrix_sync(fbh[tj], Whi + wb + wn * 32 + tj * 16, LDW);
            wmma::load_matrix_sync(fbl[tj], Wlo + wb + wn * 32 + tj * 16, LDW);
        }
#pragma unroll
        for (int ti = 0; ti < 2; ti++)
#pragma unroll
            for (int tj = 0; tj < 2; tj++) {
                wmma::mma_sync(acc[ti][tj], fah[ti], fbh[tj], acc[ti][tj]);
                wmma::mma_sync(acc[ti][tj], fah[ti], fbl[tj], acc[ti][tj]);
                wmma::mma_sync(acc[ti][tj], fal[ti], fbh[tj], acc[ti][tj]);
            }

        if (kt < 63) {
            const int nb = (cur ^ 1) * 128 * LDA;
            const int nw = (cur ^ 1) * 16 * LDW;
            cvt_store4(Ahi + nb + ar * LDA + ac, Alo + nb + ar * LDA + ac, ra0);
            cvt_store4(Ahi + nb + (ar + 64) * LDA + ac, Alo + nb + (ar + 64) * LDA + ac, ra1);
            cvt_store4(Whi + nw + wr * LDW + wc, Wlo + nw + wr * LDW + wc, rw);
        }
        __syncthreads();
    }

#pragma unroll
    for (int ti = 0; ti < 2; ti++)
#pragma unroll
        for (int tj = 0; tj < 2; tj++)
            wmma::store_matrix_sync(&stg[(wm * 32 + ti * 16) * LDST + wn * 32 + tj * 16],
                                    acc[ti][tj], LDST, wmma::mem_row_major);
    __syncthreads();

    if (MODE == 2) {
        const int b = z >> 4, h = z & 15;
#pragma unroll
        for (int i = tid; i < 2048; i += 256) {
            int r = i >> 4, c4 = (i & 15) * 4;
            float4 v = *(float4*)&stg[r * LDST + c4];
            *(float4*)&C[((size_t)(b * Sc + row0 + r)) * HDc + h * DVc + c4] = v;
        }
    } else {
        float4 bi = *(const float4*)&bias[col0 + ((tid & 15) * 4)];
#pragma unroll
        for (int i = tid; i < 2048; i += 256) {
            int r = i >> 4, c4 = (i & 15) * 4;
            float4 v = *(float4*)&stg[r * LDST + c4];
            v.x += bi.x; v.y += bi.y; v.z += bi.z; v.w += bi.w;
            if (MODE == 0) {
                *(float4*)&C[(size_t)(row0 + r) * 1024 + col0 + c4] = v;
            } else {
                int b = (row0 + r) >> 10, s = (row0 + r) & 1023;
                int h = blockIdx.x;
                *(float4*)&C[(((size_t)b * Hc + h) * Sc + s) * 64 + c4] = v;
            }
        }
    }
}

// ---------------------------------------------------------------------------
// Fused scores + mask + softmax: one block = 32 q-rows of one (b,h), full K.
// Split-bf16 QK^T into a 32x1024 fp32 smem buffer, then mask+scale+softmax,
// write normalized probs to gmem once.
// Dyn smem: Sbuf 32x1032 f32 + Q hi/lo 32x72 bf16 + K hi/lo 64x72 bf16.
// ---------------------------------------------------------------------------
#define LDS_F 1032
#define LDT_F 72
#define FUSED_SMEM (32 * LDS_F * 4 + 2 * 32 * LDT_F * 2 + 2 * 64 * LDT_F * 2)

__global__ __launch_bounds__(256)
void fused_scores_softmax(const float* __restrict__ Qp, const float* __restrict__ Kp,
                          const void* __restrict__ mask, float* __restrict__ attn) {
    extern __shared__ __align__(16) char dbuf[];
    float* Sbuf = (float*)dbuf;                              // [32][1032]
    __nv_bfloat16* Qhi = (__nv_bfloat16*)(dbuf + 32 * LDS_F * 4);
    __nv_bfloat16* Qlo = Qhi + 32 * LDT_F;
    __nv_bfloat16* Khi = Qlo + 32 * LDT_F;                   // [64][72]
    __nv_bfloat16* Klo = Khi + 64 * LDT_F;

    const int z = blockIdx.y;            // b*H + h
    const int b = z >> 4;
    const int q0 = blockIdx.x * 32;
    const int tid = threadIdx.x;
    const int w = tid >> 5;
    const int lane = tid & 31;
    const int wm = w & 1;                // q half (16 rows)
    const int wn = w >> 1;               // k strip (16 cols)

    const float* Qb = Qp + (size_t)z * Sc * DKc;
    const float* Kb = Kp + (size_t)z * Sc * DKc;

    // Load + convert Q tile (32x64)
#pragma unroll
    for (int i = tid; i < 512; i += 256) {
        int r = i >> 4, c = (i & 15) * 4;
        float4 q4 = *(const float4*)&Qb[(size_t)(q0 + r) * 64 + c];
        cvt_store4(Qhi + r * LDT_F + c, Qlo + r * LDT_F + c, q4);
    }

    for (int kt = 0; kt < 16; kt++) {
        // Load + convert K tile (64x64)
#pragma unroll
        for (int i = tid; i < 1024; i += 256) {
            int r = i >> 4, c = (i & 15) * 4;
            float4 k4 = *(const float4*)&Kb[(size_t)(kt * 64 + r) * 64 + c];
            cvt_store4(Khi + r * LDT_F + c, Klo + r * LDT_F + c, k4);
        }
        __syncthreads();

        bfrag_c acc;
        wmma::fill_fragment(acc, 0.0f);
#pragma unroll
        for (int ks = 0; ks < 4; ks++) {
            const int kb = ks * 16;
            bfrag_a fah, fal;
            bfrag_bc fbh, fbl;
            wmma::load_matrix_sync(fah, Qhi + (wm * 16) * LDT_F + kb, LDT_F);
            wmma::load_matrix_sync(fal, Qlo + (wm * 16) * LDT_F + kb, LDT_F);
            wmma::load_matrix_sync(fbh, Khi + (wn * 16) * LDT_F + kb, LDT_F);
            wmma::load_matrix_sync(fbl, Klo + (wn * 16) * LDT_F + kb, LDT_F);
            wmma::mma_sync(acc, fah, fbh, acc);
            wmma::mma_sync(acc, fah, fbl, acc);
            wmma::mma_sync(acc, fal, fbh, acc);
        }
        wmma::store_matrix_sync(&Sbuf[(wm * 16) * LDS_F + kt * 64 + wn * 16], acc,
                                LDS_F, wmma::mem_row_major);
        __syncthreads();
    }

    // Mask + scale + softmax: warp w owns rows [w*4, w*4+4)
    const int mode = g_mask_mode;
    const int* mi = (const int*)mask;
    const unsigned char* mb8 = (const unsigned char*)mask;
    const float* mf = (const float*)mask;

    for (int rr = 0; rr < 4; rr++) {
        const int r = w * 4 + rr;
        const int q = q0 + r;
        float* Srow = Sbuf + r * LDS_F;
        const size_t mrow = (size_t)b * Sc * Sc + (size_t)q * Sc;

        // pass 1: apply mask+scale, find max
        float mx = -3.0e38f;
#pragma unroll
        for (int i = 0; i < 32; i++) {
            int k = lane + i * 32;
            bool masked;
            if (mode == 0)      masked = (mi[mrow + k] != 0);
            else if (mode == 2) masked = (mf[mrow + k] != 0.0f);
            else                masked = (mb8[mrow + k] != 0);
            float v = masked ? -1e9f : Srow[k] * 0.125f;
            Srow[k] = v;
            mx = fmaxf(mx, v);
        }
#pragma unroll
        for (int o = 16; o; o >>= 1) mx = fmaxf(mx, __shfl_xor_sync(0xffffffffu, mx, o));

        // pass 2: exp + sum
        float sum = 0.0f;
#pragma unroll
        for (int i = 0; i < 32; i++) {
            int k = lane + i * 32;
            float e = expf(Srow[k] - mx);
            Srow[k] = e;
            sum += e;
        }
#pragma unroll
        for (int o = 16; o; o >>= 1) sum += __shfl_xor_sync(0xffffffffu, sum, o);
        float inv = 1.0f / sum;

        // pass 3: write normalized probs (vectorized)
        float4* dst = (float4*)(attn + ((size_t)z * Sc + q) * Sc);
#pragma unroll
        for (int i = 0; i < 8; i++) {
            int k4 = lane + i * 32;
            float4 v = *(float4*)&Srow[k4 * 4];
            v.x *= inv; v.y *= inv; v.z *= inv; v.w *= inv;
            dst[k4] = v;
        }
    }
}

// ---------------------------------------------------------------------------
// Fused residual add + LayerNorm, vectorized.
// ---------------------------------------------------------------------------
__global__ __launch_bounds__(256)
void layernorm_kernel(const float* __restrict__ x, const float* __restrict__ resid,
                      float* __restrict__ out) {
    const size_t row = blockIdx.x;
    const float4* xr = (const float4*)(x + row * Dc);
    const float4* rr = (const float4*)(resid + row * Dc);
    float4* orow = (float4*)(out + row * Dc);
    const int tid = threadIdx.x;
    const int lane = tid & 31, wid = tid >> 5;
    __shared__ float sm[16];

    float4 a = xr[tid], b = rr[tid];
    float4 v = make_float4(a.x + b.x, a.y + b.y, a.z + b.z, a.w + b.w);
    float s = (v.x + v.y) + (v.z + v.w);
#pragma unroll
    for (int o = 16; o; o >>= 1) s += __shfl_xor_sync(0xffffffffu, s, o);
    if (lane == 0) sm[wid] = s;
    __syncthreads();
    float tot = 0.0f;
#pragma unroll
    for (int i = 0; i < 8; i++) tot += sm[i];
    float mean = tot * (1.0f / 1024.0f);

    float dx = v.x - mean, dy = v.y - mean, dz = v.z - mean, dw = v.w - mean;
    float vs = (dx * dx + dy * dy) + (dz * dz + dw * dw);
#pragma unroll
    for (int o = 16; o; o >>= 1) vs += __shfl_xor_sync(0xffffffffu, vs, o);
    if (lane == 0) sm[8 + wid] = vs;
    __syncthreads();
    float vtot = 0.0f;
#pragma unroll
    for (int i = 0; i < 8; i++) vtot += sm[8 + i];
    float inv = rsqrtf(vtot * (1.0f / 1024.0f) + 1e-5f);
    orow[tid] = make_float4(dx * inv, dy * inv, dz * inv, dw * inv);
}

// ---------------------------------------------------------------------------
// Launch
// ---------------------------------------------------------------------------
extern "C" void kernel_launch(void* const* d_in, const int* in_sizes, int n_in,
                              void* d_out, int out_size) {
    const float* q    = (const float*)d_in[0];
    const float* k    = (const float*)d_in[1];
    const float* v    = (const float*)d_in[2];
    const void*  mask = d_in[3];
    const float* Wq   = (const float*)d_in[4];
    const float* bq   = (const float*)d_in[5];
    const float* Wk   = (const float*)d_in[6];
    const float* bk   = (const float*)d_in[7];
    const float* Wv   = (const float*)d_in[8];
    const float* bv   = (const float*)d_in[9];
    const float* Wo   = (const float*)d_in[10];
    const float* bo   = (const float*)d_in[11];
    float* out = (float*)d_out;

    float *Qp, *Kp, *Vp, *ctx, *obuf, *attn_fb;
    cudaGetSymbolAddress((void**)&Qp, g_Qp);
    cudaGetSymbolAddress((void**)&Kp, g_Kp);
    cudaGetSymbolAddress((void**)&Vp, g_Vp);
    cudaGetSymbolAddress((void**)&ctx, g_ctx);
    cudaGetSymbolAddress((void**)&obuf, g_obuf);
    cudaGetSymbolAddress((void**)&attn_fb, g_attn_fb);

    const long long LN_ELEMS = (long long)Mc * Dc;
    const long long ATTN_ELEMS = (long long)Bc * Hc * Sc * Sc;
    float* attn = ((long long)out_size >= LN_ELEMS + ATTN_ELEMS)
                      ? (out + (size_t)LN_ELEMS)
                      : attn_fb;

    static int smem_set = 0;
    if (!smem_set) {
        cudaFuncSetAttribute(fused_scores_softmax,
                             cudaFuncAttributeMaxDynamicSharedMemorySize, FUSED_SMEM);
        smem_set = 1;
    }

    detect_mask_kernel<<<1, 1>>>((const unsigned int*)mask);

    // Projections (split-bf16, pipelined)
    gemm_bf16_split<1><<<dim3(16, 32), 256>>>(q, Wq, bq, Qp, HDc);
    gemm_bf16_split<1><<<dim3(16, 32), 256>>>(k, Wk, bk, Kp, HDc);
    gemm_bf16_split<1><<<dim3(16, 32), 256>>>(v, Wv, bv, Vp, HDc);

    // Fused scores + mask + softmax -> normalized probs (written once)
    fused_scores_softmax<<<dim3(32, Bc * Hc), 256, FUSED_SMEM>>>(Qp, Kp, mask, attn);

    // Context GEMM (split-bf16) -> concat layout
    gemm_bf16_split<2><<<dim3(8, 64), 256>>>(attn, Vp, nullptr, ctx, DVc);

    // Output projection (split-bf16)
    gemm_bf16_split<0><<<dim3(16, 32), 256>>>(ctx, Wo, bo, obuf, Dc);

    // Residual + LayerNorm
    layernorm_kernel<<<Mc, 256>>>(obuf, q, out);
}